// round 1
// baseline (speedup 1.0000x reference)
#include <cuda_runtime.h>

// out[b, :] = table_bits[idx(b), :]  where idx(b) = sum_k idx_bits[b,k] << (5-k)
// table_bits: [64, 64] f32 (16 KB), idx_bits: [262144, 6] i32, out: [262144, 64] f32.

#define BATCH 262144
#define THREADS 256

__global__ __launch_bounds__(THREADS)
void spike_lookup_kernel(const float4* __restrict__ table4,   // 64*16 float4
                         const int*    __restrict__ bits,     // BATCH*6
                         float4*       __restrict__ out4)     // BATCH*16
{
    __shared__ float4 t[64 * 16];   // 16 KB table, row r at t[r*16 .. r*16+15]

    // Cooperative table load: 1024 float4 across 256 threads.
    #pragma unroll
    for (int i = threadIdx.x; i < 64 * 16; i += THREADS)
        t[i] = table4[i];
    __syncthreads();

    int gid = blockIdx.x * THREADS + threadIdx.x;   // one thread per output float4
    int b = gid >> 4;                               // batch element
    int j = gid & 15;                               // float4 column within row

    const int* __restrict__ p = bits + b * 6;
    // bits are 0/1 int32, MSB first (k=0 has weight 32)
    int idx = (p[0] << 5) | (p[1] << 4) | (p[2] << 3)
            | (p[3] << 2) | (p[4] << 1) |  p[5];

    out4[gid] = t[idx * 16 + j];
}

extern "C" void kernel_launch(void* const* d_in, const int* in_sizes, int n_in,
                              void* d_out, int out_size)
{
    const float4* table4 = (const float4*)d_in[0];   // table_bits [64,64] f32
    const int*    bits   = (const int*)d_in[1];      // idx_bits [BATCH,6] i32
    float4*       out4   = (float4*)d_out;           // [BATCH,64] f32

    const int total_threads = BATCH * 16;            // one float4 per thread
    const int grid = total_threads / THREADS;        // 16384 blocks

    spike_lookup_kernel<<<grid, THREADS>>>(table4, bits, out4);
}

// round 2
// speedup vs baseline: 1.6584x; 1.6584x over previous
#include <cuda_runtime.h>

// out[b, :] = table_bits[idx(b), :],  idx(b) = sum_k idx_bits[b,k] << (5-k)
// table_bits: [64,64] f32 of 0/1 pulses -> packed once into 64-bit masks.
// idx_bits: [262144, 6] i32 of 0/1.  out: [262144, 64] f32.

#define BATCH 262144
#define THREADS 256

// Packed table: row r -> {hi, lo}; column c lives at bit (31 - (c&31)) of (c<32 ? hi : lo).
__device__ uint2 g_masks[64];

__global__ void build_masks_kernel(const float* __restrict__ table)
{
    int warp = (blockIdx.x * blockDim.x + threadIdx.x) >> 5;   // 0..63 = table row
    int lane = threadIdx.x & 31;
    float v0 = table[warp * 64 + lane];        // columns 0..31
    float v1 = table[warp * 64 + 32 + lane];   // columns 32..63
    unsigned hi = __brev(__ballot_sync(0xFFFFFFFFu, v0 > 0.5f));  // col c -> bit 31-c
    unsigned lo = __brev(__ballot_sync(0xFFFFFFFFu, v1 > 0.5f));
    if (lane == 0) g_masks[warp] = make_uint2(hi, lo);
}

__global__ __launch_bounds__(THREADS)
void spike_lookup_kernel(const int* __restrict__ bits,    // BATCH*6
                         float4*    __restrict__ out4)    // BATCH*16
{
    int warp_g = (blockIdx.x * THREADS + threadIdx.x) >> 5;  // covers 2 batch rows
    int lane   = threadIdx.x & 31;

    // One coalesced LDG for the 12 index ints of both rows, then ballot+brev.
    int v = 0;
    if (lane < 12) v = bits[warp_g * 12 + lane];
    unsigned m  = __brev(__ballot_sync(0xFFFFFFFFu, v != 0)); // lane l -> bit 31-l
    // lanes 0..15 handle row 2w (bits in lanes 0..5), lanes 16..31 row 2w+1 (lanes 6..11)
    int idx = (lane < 16) ? ((m >> 26) & 63) : ((m >> 20) & 63);

    uint2 msk = g_masks[idx];                 // 8B broadcast load (<=2 lines/warp)

    int j   = lane & 15;                      // float4 column within the 64-bit row
    unsigned word = (j < 8) ? msk.x : msk.y;
    unsigned nib  = (word >> (28 - 4 * (j & 7))) & 0xF;  // bit3 = first (MSB) column

    float4 o;
    o.x = (nib & 8u) ? 1.0f : 0.0f;
    o.y = (nib & 4u) ? 1.0f : 0.0f;
    o.z = (nib & 2u) ? 1.0f : 0.0f;
    o.w = (nib & 1u) ? 1.0f : 0.0f;

    out4[((warp_g * 2 + (lane >> 4)) * 16) + j] = o;
}

extern "C" void kernel_launch(void* const* d_in, const int* in_sizes, int n_in,
                              void* d_out, int out_size)
{
    const float* table = (const float*)d_in[0];
    const int*   bits  = (const int*)d_in[1];
    float4*      out4  = (float4*)d_out;

    build_masks_kernel<<<2, 1024>>>(table);                 // 64 warps, one per row

    const int total_threads = BATCH * 16;                   // one float4 per thread
    spike_lookup_kernel<<<total_threads / THREADS, THREADS>>>(bits, out4);
}